// round 9
// baseline (speedup 1.0000x reference)
#include <cuda_runtime.h>
#include <cuda_bf16.h>
#include <cstdint>

// Deformable Conv3d via portable HMMA (mma.sync.m16n8k16.bf16, hi/lo split).
// R9: software-pipelined tap loop — within each iteration, the gathers for
//     tap k+1 are ISSUED, then a chunk of tap-k MMA work executes while they
//     are in flight, then the gathers are CONSUMED (4 point-pair / k-step
//     slices per tap). One pair-barrier per tap. B staged per 10-tap phase.

namespace {
constexpr int B_ = 2, CIN_ = 64, COUT_ = 64, D_ = 8, H_ = 32, W_ = 32, K_ = 27;
constexpr int P_ = D_ * H_ * W_;              // 8192
constexpr int MTILE = 128;
constexpr int THREADS = 512;
constexpr int NBLK = (B_ * P_) / MTILE;       // 128
constexpr int PH   = 10;                      // taps per B phase (10,10,7)

constexpr int SM_B     = 2 * 32768;           // A: [buf][hi 16K | lo 16K]
constexpr int SM_TOTAL = SM_B + PH * 16384;   // 229376 (224KB)
constexpr unsigned FULL = 0xffffffffu;
}

__device__ __align__(256) float g_xT[B_ * P_ * CIN_];            // channels-last x
// B images, ldmatrix layout: [kt][j(8)][ks(4)][hl(2)][kh(2)][row(8)][16B]
__device__ __align__(256) unsigned char g_wB[K_ * 16384];

// ---------------- helpers ----------------
__device__ __forceinline__ uint32_t smem_u32(const void* p) {
    uint32_t a;
    asm("{ .reg .u64 t; cvta.to.shared.u64 t, %1; cvt.u32.u64 %0, t; }"
        : "=r"(a) : "l"(p));
    return a;
}
__device__ __forceinline__ uint32_t bf16x2(float hi_elem, float lo_elem) {
    uint32_t r;
    asm("cvt.rn.bf16x2.f32 %0, %1, %2;" : "=r"(r) : "f"(hi_elem), "f"(lo_elem));
    return r;
}
__device__ __forceinline__ void ldm_x4(uint32_t* r, uint32_t addr) {
    asm volatile("ldmatrix.sync.aligned.m8n8.x4.shared.b16 {%0,%1,%2,%3}, [%4];"
                 : "=r"(r[0]), "=r"(r[1]), "=r"(r[2]), "=r"(r[3]) : "r"(addr));
}
__device__ __forceinline__ void mma_bf16(float* c, const uint32_t* a,
                                         const uint32_t* b) {
    asm volatile(
        "mma.sync.aligned.m16n8k16.row.col.f32.bf16.bf16.f32 "
        "{%0,%1,%2,%3}, {%4,%5,%6,%7}, {%8,%9}, {%0,%1,%2,%3};"
        : "+f"(c[0]), "+f"(c[1]), "+f"(c[2]), "+f"(c[3])
        : "r"(a[0]), "r"(a[1]), "r"(a[2]), "r"(a[3]), "r"(b[0]), "r"(b[1]));
}
__device__ __forceinline__ void bar_pair(int id) {
    asm volatile("bar.sync %0, 64;" :: "r"(id) : "memory");
}

// per-point in-flight gather state (registers)
struct PtFlight {
    float4 v0, v1, v2, v3;
    float g0, g1, g2, g3;
};

// compute weights/addresses from offsets and ISSUE the 4 gathers
__device__ __forceinline__ void issue_pt(
    const char* base2, int half, int p, int kd, int kh3, int kw3,
    float od_, float oh_, float ow_, PtFlight& f)
{
    const int od = p >> 10, oh = (p >> 5) & 31, ow = p & 31;
    float zd = (float)(od - 1 + kd)  + od_;
    float zh = (float)(oh - 1 + kh3) + oh_;
    float zw = (float)(ow - 1 + kw3) + ow_;

    float fd = floorf(zd); int d0 = (int)fd; float rd = zd - fd;
    float fh = floorf(zh); int h0 = (int)fh; float rh = zh - fh;
    float fw = floorf(zw); int w0 = (int)fw; float rw = zw - fw;

    float wd = half ? (((unsigned)(d0 + 1) < (unsigned)D_) ? rd : 0.f)
                    : (((unsigned)d0 < (unsigned)D_) ? 1.f - rd : 0.f);
    float wh0 = ((unsigned)h0       < (unsigned)H_) ? 1.f - rh : 0.f;
    float wh1 = ((unsigned)(h0 + 1) < (unsigned)H_) ? rh       : 0.f;
    float ww0 = ((unsigned)w0       < (unsigned)W_) ? 1.f - rw : 0.f;
    float ww1 = ((unsigned)(w0 + 1) < (unsigned)W_) ? rw       : 0.f;

    const int s0 = (d0 + half) * 1024 + h0 * 32 + w0;
    const uint32_t i0 = ((uint32_t)s0        & 8191u) << 8;
    const uint32_t i1 = ((uint32_t)(s0 + 1)  & 8191u) << 8;
    const uint32_t i2 = ((uint32_t)(s0 + 32) & 8191u) << 8;
    const uint32_t i3 = ((uint32_t)(s0 + 33) & 8191u) << 8;

    const float wdh0 = wd * wh0, wdh1 = wd * wh1;
    f.g0 = wdh0 * ww0; f.g1 = wdh0 * ww1;
    f.g2 = wdh1 * ww0; f.g3 = wdh1 * ww1;

    f.v0 = __ldg(reinterpret_cast<const float4*>(base2 + i0));
    f.v1 = __ldg(reinterpret_cast<const float4*>(base2 + i1));
    f.v2 = __ldg(reinterpret_cast<const float4*>(base2 + i2));
    f.v3 = __ldg(reinterpret_cast<const float4*>(base2 + i3));
}

// reduce corners, combine halves, bf16-split, store to A tile
__device__ __forceinline__ void consume_pt(
    const PtFlight& f, int half, char* AhP, char* AlP, uint32_t stoff)
{
    float ax = f.g0 * f.v0.x + f.g1 * f.v1.x + f.g2 * f.v2.x + f.g3 * f.v3.x;
    float ay = f.g0 * f.v0.y + f.g1 * f.v1.y + f.g2 * f.v2.y + f.g3 * f.v3.y;
    float az = f.g0 * f.v0.z + f.g1 * f.v1.z + f.g2 * f.v2.z + f.g3 * f.v3.z;
    float aw = f.g0 * f.v0.w + f.g1 * f.v1.w + f.g2 * f.v2.w + f.g3 * f.v3.w;

    ax += __shfl_down_sync(FULL, ax, 16);
    ay += __shfl_down_sync(FULL, ay, 16);
    az += __shfl_down_sync(FULL, az, 16);
    aw += __shfl_down_sync(FULL, aw, 16);

    if (half == 0) {
        uint32_t h01 = bf16x2(ay, ax);       // hi=ch+1, lo=ch+0
        uint32_t h23 = bf16x2(aw, az);
        float hx = __uint_as_float(h01 << 16);
        float hy = __uint_as_float(h01 & 0xffff0000u);
        float hz = __uint_as_float(h23 << 16);
        float hww = __uint_as_float(h23 & 0xffff0000u);
        uint32_t l01 = bf16x2(ay - hy, ax - hx);
        uint32_t l23 = bf16x2(aw - hww, az - hz);
        *reinterpret_cast<uint2*>(AhP + stoff) = make_uint2(h01, h23);
        *reinterpret_cast<uint2*>(AlP + stoff) = make_uint2(l01, l23);
    }
}

// ---------------- prep ----------------
__global__ void prep_kernel(const float* __restrict__ x,
                            const float* __restrict__ w) {
    const int stride = gridDim.x * blockDim.x;
    const int tid = blockIdx.x * blockDim.x + threadIdx.x;

    for (int i = tid; i < B_ * CIN_ * P_; i += stride) {
        int s = i % P_;
        int c = (i / P_) % CIN_;
        int b = i / (P_ * CIN_);
        g_xT[(b * P_ + s) * CIN_ + c] = x[i];
    }

    for (int i = tid; i < K_ * COUT_ * CIN_; i += stride) {
        int c  = i % CIN_;
        int n  = (i / CIN_) % COUT_;
        int kt = i / (CIN_ * COUT_);
        float v = w[(n * CIN_ + c) * K_ + kt];
        __nv_bfloat16 hi = __float2bfloat16(v);
        __nv_bfloat16 lo = __float2bfloat16(v - __bfloat162float(hi));
        int j = n >> 3, r = n & 7, ks = c >> 4, kh = (c >> 3) & 1, col = c & 7;
        size_t base = (size_t)kt * 16384 + (size_t)j * 2048 + (size_t)ks * 512;
        size_t off  = (size_t)kh * 128 + (size_t)r * 16 + (size_t)col * 2;
        *reinterpret_cast<__nv_bfloat16*>(g_wB + base + off)       = hi;
        *reinterpret_cast<__nv_bfloat16*>(g_wB + base + 256 + off) = lo;
    }
}

// ---------------- main ----------------
__global__ __launch_bounds__(THREADS, 1)
void deform_hmma_kernel(const float* __restrict__ offset,
                        const float* __restrict__ bias,
                        float* __restrict__ out) {
    extern __shared__ __align__(1024) char smem[];
    const uint32_t sb = smem_u32(smem);

    const int tid  = threadIdx.x;
    const int lane = tid & 31;
    const int warp = tid >> 5;               // 16 warps
    const int blk  = blockIdx.x;
    const int b    = blk >> 6;
    const int p0   = (blk & 63) * MTILE;

    const float* offB = offset + (size_t)b * 3 * K_ * P_;
    const char*  xb   = reinterpret_cast<const char*>(g_xT + (size_t)b * P_ * CIN_);

    const int half = lane >> 4;
    const int c4   = lane & 15;
    const int pl_base = warp * 8;
    const char* base2 = xb + (uint32_t)(c4 << 4);
    uint32_t wAoff[8];
#pragma unroll
    for (int i = 0; i < 8; i++) {
        int pl = pl_base + i;
        wAoff[i] = (uint32_t)(pl * 128 + ((c4 * 8) ^ ((pl & 7) << 4)));
    }

    const int mt = warp >> 1, nt = warp & 1;
    const int rowA = mt * 16 + (lane & 15);
    const uint32_t aBaseOff = (uint32_t)(rowA * 128);
    const uint32_t aXor = (uint32_t)((rowA & 7) << 4);
    const uint32_t aKh  = (uint32_t)((lane >> 4) << 4);
    const uint32_t bLane = (uint32_t)(((lane >> 3) << 7) + ((lane & 7) << 4));

    float acc[4][4];
#pragma unroll
    for (int j = 0; j < 4; j++)
#pragma unroll
        for (int q = 0; q < 4; q++) acc[j][q] = 0.f;

    // ---- prologue: sample tap 0 into buf 0 ----
    {
        char* AhP = smem;                // buf 0
        char* AlP = AhP + 16384;
        const float* offk = offB;        // kt = 0
#pragma unroll
        for (int i = 0; i < 8; i++) {
            const int p = p0 + pl_base + i;
            PtFlight f;
            issue_pt(base2, half, p, 0, 0, 0,
                     __ldg(offk + p), __ldg(offk + P_ + p), __ldg(offk + 2 * P_ + p), f);
            consume_pt(f, half, AhP, AlP, wAoff[i]);
        }
        bar_pair(mt + 1);
    }

#pragma unroll 1
    for (int kt = 0; kt < K_; kt++) {
        const int buf = kt & 1;
        const uint32_t AhB = sb + buf * 32768;      // read side (tap kt)
        const uint32_t AlB = AhB + 16384;
        char* AhW = smem + (buf ^ 1) * 32768;       // write side (tap kt+1)
        char* AlW = AhW + 16384;
        const int t = kt % PH;
        const uint32_t Bt = sb + SM_B + t * 16384;

        // B phase staging (3x per kernel)
        if (t == 0) {
            __syncthreads();
            const int kt0 = kt;
            const int ph_len = (kt0 + PH <= K_) ? PH : (K_ - kt0);
            const uint4* src = reinterpret_cast<const uint4*>(g_wB + (size_t)kt0 * 16384);
            uint4* dst = reinterpret_cast<uint4*>(smem + SM_B);
            const int nvec = ph_len * 1024;
            for (int i = tid; i < nvec; i += THREADS)
                dst[i] = __ldg(&src[i]);
            __syncthreads();
        }

        const bool more = (kt + 1 < K_);
        const int kn = more ? kt + 1 : kt;
        const int kd = kn / 9, kh3 = (kn / 3) % 3, kw3 = kn % 3;
        const float* offk = offB + 3 * kn * P_;

        // prefetch offsets for all 8 points of tap kn
        float ofd[8], ofh[8], ofw[8];
        if (more) {
#pragma unroll
            for (int i = 0; i < 8; i++) {
                const int p = p0 + pl_base + i;
                ofd[i] = __ldg(offk + p);
                ofh[i] = __ldg(offk + P_ + p);
                ofw[i] = __ldg(offk + 2 * P_ + p);
            }
        }

        // ---- interleaved: 4 slices of [issue pair | mma k-step | consume pair] ----
#pragma unroll
        for (int q = 0; q < 4; q++) {
            PtFlight f0, f1;
            if (more) {
                const int i0 = 2 * q, i1 = 2 * q + 1;
                issue_pt(base2, half, p0 + pl_base + i0, kd, kh3, kw3,
                         ofd[i0], ofh[i0], ofw[i0], f0);
                issue_pt(base2, half, p0 + pl_base + i1, kd, kh3, kw3,
                         ofd[i1], ofh[i1], ofw[i1], f1);
            }

            // mma chunk: k-step q of tap kt
            {
                uint32_t ah[4], al[4];
                const uint32_t aoff = aBaseOff + (((uint32_t)(q * 32) + aKh) ^ aXor);
                ldm_x4(ah, AhB + aoff);
                ldm_x4(al, AlB + aoff);
#pragma unroll
                for (int j = 0; j < 4; j++) {
                    uint32_t bb[4];      // hi-b0, hi-b1, lo-b0, lo-b1
                    ldm_x4(bb, Bt + (uint32_t)((nt * 4 + j) * 2048 + q * 512) + bLane);
                    mma_bf16(acc[j], ah, &bb[0]);   // Ah*Bh
                    mma_bf16(acc[j], al, &bb[0]);   // Al*Bh
                    mma_bf16(acc[j], ah, &bb[2]);   // Ah*Bl
                }
            }

            if (more) {
                consume_pt(f0, half, AhW, AlW, wAoff[2 * q]);
                consume_pt(f1, half, AhW, AlW, wAoff[2 * q + 1]);
            }
        }

        bar_pair(mt + 1);   // orders STS(kt+1) before ldsm(kt+1); WAR on buf
    }

    // ---- epilogue: D fragment scatter + bias ----
    const int m = lane >> 2;
    const int p = p0 + mt * 16 + m;
#pragma unroll
    for (int j = 0; j < 4; j++) {
        const int n = nt * 32 + j * 8 + 2 * (lane & 3);
        const float bv0 = __ldg(&bias[n]);
        const float bv1 = __ldg(&bias[n + 1]);
        float* o0 = out + ((size_t)(b * COUT_ + n)) * P_ + p;
        o0[0]      = acc[j][0] + bv0;
        o0[P_]     = acc[j][1] + bv1;
        o0[8]      = acc[j][2] + bv0;
        o0[P_ + 8] = acc[j][3] + bv1;
    }
}

extern "C" void kernel_launch(void* const* d_in, const int* in_sizes, int n_in,
                              void* d_out, int out_size) {
    const float* x      = (const float*)d_in[0];
    const float* offset = (const float*)d_in[1];
    const float* weight = (const float*)d_in[2];
    const float* bias   = (const float*)d_in[3];
    float* out = (float*)d_out;

    cudaFuncSetAttribute(deform_hmma_kernel,
                         cudaFuncAttributeMaxDynamicSharedMemorySize, SM_TOTAL);
    prep_kernel<<<256, 256>>>(x, weight);
    deform_hmma_kernel<<<NBLK, THREADS, SM_TOTAL>>>(offset, bias, out);
}